// round 10
// baseline (speedup 1.0000x reference)
#include <cuda_runtime.h>
#include <cstdint>

#define NHEADS   16
#define M_TBL    524288
#define D_IN     32
#define HID      64
#define NOUT     3
#define THREADS  128
#define NPOINTS  2097152
#define BLOCKS   (NPOINTS / THREADS)   // 16384

__constant__ __align__(16) float cW1[D_IN * HID];
__constant__ __align__(16) float cW2[HID * HID];
__constant__ __align__(16) float cW3[HID * HID];
__constant__ __align__(16) float cW4[HID * NOUT];
__constant__ __align__(16) float cb1[HID];
__constant__ __align__(16) float cb2[HID];
__constant__ __align__(16) float cb3[HID];
__constant__ __align__(16) float cb4[NOUT];

typedef unsigned long long ull;

#define FMA2(acc, a, w) \
    asm("fma.rn.f32x2 %0, %1, %2, %0;" : "+l"(acc) : "l"(a), "l"(w))
#define PACK2(d, s) \
    asm("mov.b64 %0, {%1, %1};" : "=l"(d) : "f"(s))
#define UNPACK2(lo, hi, s) \
    asm("mov.b64 {%0, %1}, %2;" : "=f"(lo), "=f"(hi) : "l"(s))

// One hidden layer (64->64) entirely in registers.
// hin[32]: previous layer's outputs as f32x2 j-pairs (pre-relu).
// hout[32]: this layer's outputs as f32x2 j-pairs (pre-relu).
// relu is folded into the scalar extraction of each input.
// Weight loads: &cW[k*64 + 4q] -> warp-uniform LDCU.128 (16 per k).
template<const float* /*unused*/ dummy = nullptr>
struct Dummy {};

__device__ __forceinline__ void hidden_layer(const ull hin[32], ull hout[32],
                                             const float* __restrict__ W,
                                             const float* __restrict__ bias)
{
    #pragma unroll
    for (int jp = 0; jp < 32; jp++)
        hout[jp] = *reinterpret_cast<const ull*>(&bias[2 * jp]);

    #pragma unroll 4
    for (int k2 = 0; k2 < 32; k2++) {
        float alo, ahi;
        UNPACK2(alo, ahi, hin[k2]);
        alo = fmaxf(alo, 0.0f);
        ahi = fmaxf(ahi, 0.0f);

        ull da;
        PACK2(da, alo);
        {
            const ulonglong2* wr =
                reinterpret_cast<const ulonglong2*>(&W[(2 * k2) * HID]);
            #pragma unroll
            for (int q = 0; q < 16; q++) {
                const ulonglong2 w = wr[q];
                FMA2(hout[2 * q],     da, w.x);
                FMA2(hout[2 * q + 1], da, w.y);
            }
        }
        PACK2(da, ahi);
        {
            const ulonglong2* wr =
                reinterpret_cast<const ulonglong2*>(&W[(2 * k2 + 1) * HID]);
            #pragma unroll
            for (int q = 0; q < 16; q++) {
                const ulonglong2 w = wr[q];
                FMA2(hout[2 * q],     da, w.x);
                FMA2(hout[2 * q + 1], da, w.y);
            }
        }
    }
}

__global__ __launch_bounds__(THREADS, 3)
void ngp_reg_kernel(const int* __restrict__ idx,
                    const float* __restrict__ tables,
                    float* __restrict__ out)
{
    const int n = blockIdx.x * THREADS + threadIdx.x;   // one point per thread

    // ---- gather: 16 heads x float2 into registers ----
    float f[D_IN];
    {
        const int* ip = idx + (long)n * NHEADS;
        int4 iv[4];
        #pragma unroll
        for (int g = 0; g < 4; g++)
            iv[g] = *reinterpret_cast<const int4*>(ip + g * 4);
        #pragma unroll
        for (int g = 0; g < 4; g++) {
            const int ii[4] = { iv[g].x, iv[g].y, iv[g].z, iv[g].w };
            #pragma unroll
            for (int q = 0; q < 4; q++) {
                const int h = g * 4 + q;
                const float2 v = *reinterpret_cast<const float2*>(
                    tables + ((long)h * M_TBL + ii[q]) * 2);
                f[2 * h]     = v.x;
                f[2 * h + 1] = v.y;
            }
        }
    }

    // ---- layer 1: 32 -> 64 (inputs raw, no relu) ----
    ull h1[32];
    #pragma unroll
    for (int jp = 0; jp < 32; jp++)
        h1[jp] = *reinterpret_cast<const ull*>(&cb1[2 * jp]);
    #pragma unroll 4
    for (int k = 0; k < D_IN; k++) {
        ull da;
        PACK2(da, f[k]);
        const ulonglong2* wr =
            reinterpret_cast<const ulonglong2*>(&cW1[k * HID]);
        #pragma unroll
        for (int q = 0; q < 16; q++) {
            const ulonglong2 w = wr[q];
            FMA2(h1[2 * q],     da, w.x);
            FMA2(h1[2 * q + 1], da, w.y);
        }
    }

    // ---- layers 2 and 3 (relu folded into input extraction) ----
    ull h2[32];
    hidden_layer(h1, h2, cW2, cb2);
    hidden_layer(h2, h1, cW3, cb3);

    // ---- layer 4: 64 -> 3 (relu folded) ----
    float o0 = cb4[0], o1 = cb4[1], o2 = cb4[2];
    #pragma unroll 8
    for (int k2 = 0; k2 < 32; k2++) {
        float alo, ahi;
        UNPACK2(alo, ahi, h1[k2]);
        alo = fmaxf(alo, 0.0f);
        ahi = fmaxf(ahi, 0.0f);
        const float* w0 = &cW4[(2 * k2) * NOUT];
        o0 = fmaf(alo, w0[0], o0);
        o1 = fmaf(alo, w0[1], o1);
        o2 = fmaf(alo, w0[2], o2);
        const float* w1 = &cW4[(2 * k2 + 1) * NOUT];
        o0 = fmaf(ahi, w1[0], o0);
        o1 = fmaf(ahi, w1[1], o1);
        o2 = fmaf(ahi, w1[2], o2);
    }

    float* op = out + (long)n * NOUT;
    op[0] = o0;
    op[1] = o1;
    op[2] = o2;
}

extern "C" void kernel_launch(void* const* d_in, const int* in_sizes, int n_in,
                              void* d_out, int out_size)
{
    cudaMemcpyToSymbolAsync(cW1, d_in[2], D_IN*HID*sizeof(float), 0,
                            cudaMemcpyDeviceToDevice, 0);
    cudaMemcpyToSymbolAsync(cb1, d_in[3], HID*sizeof(float), 0,
                            cudaMemcpyDeviceToDevice, 0);
    cudaMemcpyToSymbolAsync(cW2, d_in[4], HID*HID*sizeof(float), 0,
                            cudaMemcpyDeviceToDevice, 0);
    cudaMemcpyToSymbolAsync(cb2, d_in[5], HID*sizeof(float), 0,
                            cudaMemcpyDeviceToDevice, 0);
    cudaMemcpyToSymbolAsync(cW3, d_in[6], HID*HID*sizeof(float), 0,
                            cudaMemcpyDeviceToDevice, 0);
    cudaMemcpyToSymbolAsync(cb3, d_in[7], HID*sizeof(float), 0,
                            cudaMemcpyDeviceToDevice, 0);
    cudaMemcpyToSymbolAsync(cW4, d_in[8], HID*NOUT*sizeof(float), 0,
                            cudaMemcpyDeviceToDevice, 0);
    cudaMemcpyToSymbolAsync(cb4, d_in[9], NOUT*sizeof(float), 0,
                            cudaMemcpyDeviceToDevice, 0);

    ngp_reg_kernel<<<BLOCKS, THREADS>>>(
        (const int*)d_in[0], (const float*)d_in[1], (float*)d_out);
}

// round 11
// speedup vs baseline: 2.9108x; 2.9108x over previous
#include <cuda_runtime.h>
#include <cstdint>

#define NHEADS   16
#define M_TBL    524288
#define D_IN     32
#define HID      64
#define NOUT     3
#define TILE     256
#define THREADS  512
#define NTILES   8192            // 8192 * 256 = 2,097,152
#define GRID     148             // persistent: 1 CTA (512 thr) per SM
#define STR      256             // no padding needed: all smem ops are same-row

__constant__ __align__(16) float cW1[D_IN * HID];
__constant__ __align__(16) float cW2[HID * HID];
__constant__ __align__(16) float cW3[HID * HID];
__constant__ __align__(16) float cW4[HID * NOUT];
__constant__ __align__(16) float cb1[HID];
__constant__ __align__(16) float cb2[HID];
__constant__ __align__(16) float cb3[HID];
__constant__ __align__(16) float cb4[NOUT];

#define BUF_FLOATS (HID * STR)               // 16384 floats = 64 KB
#define SMEM_BYTES (2 * BUF_FLOATS * 4)      // 131072 -> 1 CTA/SM

#define FMA2(acc, a, w) \
    asm("fma.rn.f32x2 %0, %1, %2, %0;" : "+l"(acc) : "l"(a), "l"(w))
#define PACK2(d, s) \
    asm("mov.b64 %0, {%1, %1};" : "=l"(d) : "f"(s))
#define UNPACK2(lo, hi, s) \
    asm("mov.b64 {%0, %1}, %2;" : "=f"(lo), "=f"(hi) : "l"(s))

typedef unsigned long long ull;

// One layer, ping-pong: read A, write B (disjoint) -> single sync after.
// Warp owns j-block [jw, jw+4). Lane owns points lane4..+3 and 128+lane4..+3.
// acc[h*8 + p*2 + jp]: h=half, p=point, jp = j-pair (jw+2jp, jw+2jp+1).
// Per k-step: 2 LDS.128 + 1 LDC.128 + 8 PACK2 + 16 FFMA2.
template<int L, int K>
__device__ __forceinline__ void layer(const float* __restrict__ A,
                                      float* __restrict__ B,
                                      int jw, int lane4)
{
    ull acc[16];
    {
        ulonglong2 b;
        if constexpr (L == 1)
            b = *reinterpret_cast<const ulonglong2*>(&cb1[jw]);
        else if constexpr (L == 2)
            b = *reinterpret_cast<const ulonglong2*>(&cb2[jw]);
        else
            b = *reinterpret_cast<const ulonglong2*>(&cb3[jw]);
        #pragma unroll
        for (int p = 0; p < 4; p++) {
            acc[p*2 + 0] = b.x; acc[p*2 + 1] = b.y;
            acc[8 + p*2 + 0] = b.x; acc[8 + p*2 + 1] = b.y;
        }
    }

    #pragma unroll 8
    for (int k = 0; k < K; k++) {
        const float4 aA = *reinterpret_cast<const float4*>(&A[k * STR + lane4]);
        const float4 aB = *reinterpret_cast<const float4*>(&A[k * STR + 128 + lane4]);
        ull dA0, dA1, dA2, dA3, dB0, dB1, dB2, dB3;
        PACK2(dA0, aA.x); PACK2(dA1, aA.y); PACK2(dA2, aA.z); PACK2(dA3, aA.w);
        PACK2(dB0, aB.x); PACK2(dB1, aB.y); PACK2(dB2, aB.z); PACK2(dB3, aB.w);

        ulonglong2 w;   // 2 natural j-pairs via 1 LDC.128 (warp-uniform)
        if constexpr (L == 1)
            w = *reinterpret_cast<const ulonglong2*>(&cW1[k * HID + jw]);
        else if constexpr (L == 2)
            w = *reinterpret_cast<const ulonglong2*>(&cW2[k * HID + jw]);
        else
            w = *reinterpret_cast<const ulonglong2*>(&cW3[k * HID + jw]);

        FMA2(acc[ 0], dA0, w.x); FMA2(acc[ 1], dA0, w.y);
        FMA2(acc[ 2], dA1, w.x); FMA2(acc[ 3], dA1, w.y);
        FMA2(acc[ 4], dA2, w.x); FMA2(acc[ 5], dA2, w.y);
        FMA2(acc[ 6], dA3, w.x); FMA2(acc[ 7], dA3, w.y);
        FMA2(acc[ 8], dB0, w.x); FMA2(acc[ 9], dB0, w.y);
        FMA2(acc[10], dB1, w.x); FMA2(acc[11], dB1, w.y);
        FMA2(acc[12], dB2, w.x); FMA2(acc[13], dB2, w.y);
        FMA2(acc[14], dB3, w.x); FMA2(acc[15], dB3, w.y);
    }

    // relu + store (disjoint from A -> no barrier needed before store)
    #pragma unroll
    for (int jp = 0; jp < 2; jp++) {
        float lo[8], hi[8];
        #pragma unroll
        for (int p = 0; p < 4; p++) {
            UNPACK2(lo[p],     hi[p],     acc[p*2 + jp]);
            UNPACK2(lo[4 + p], hi[4 + p], acc[8 + p*2 + jp]);
        }
        #pragma unroll
        for (int q = 0; q < 8; q++) {
            lo[q] = fmaxf(lo[q], 0.0f);
            hi[q] = fmaxf(hi[q], 0.0f);
        }
        const int j0 = jw + 2 * jp;
        *reinterpret_cast<float4*>(&B[j0 * STR + lane4]) =
            make_float4(lo[0], lo[1], lo[2], lo[3]);
        *reinterpret_cast<float4*>(&B[j0 * STR + 128 + lane4]) =
            make_float4(lo[4], lo[5], lo[6], lo[7]);
        *reinterpret_cast<float4*>(&B[(j0 + 1) * STR + lane4]) =
            make_float4(hi[0], hi[1], hi[2], hi[3]);
        *reinterpret_cast<float4*>(&B[(j0 + 1) * STR + 128 + lane4]) =
            make_float4(hi[4], hi[5], hi[6], hi[7]);
    }
}

__global__ __launch_bounds__(THREADS, 1)
void ngp_pp_kernel(const int* __restrict__ idx,
                   const float* __restrict__ tables,
                   float* __restrict__ out)
{
    extern __shared__ float sm[];
    float* buf0 = sm;                 // input (rows 0..31) + L2 output
    float* buf1 = sm + BUF_FLOATS;    // L1, L3 outputs

    const int tid   = threadIdx.x;
    const int wid   = tid >> 5;
    const int lane  = tid & 31;
    const int jw    = wid * 4;        // 16 warps x 4 j-cols = 64
    const int lane4 = lane * 4;
    const int gp = tid >> 1;          // gather: point (2 threads/point)
    const int gh = (tid & 1) * 8;     // gather: head start

    // ---- gather first tile into buf0 rows 0..31 ----
    {
        const int* ip = idx + ((long)blockIdx.x * TILE + gp) * NHEADS + gh;
        const int4 i0 = *reinterpret_cast<const int4*>(ip);
        const int4 i1 = *reinterpret_cast<const int4*>(ip + 4);
        const int ii[8] = { i0.x, i0.y, i0.z, i0.w, i1.x, i1.y, i1.z, i1.w };
        #pragma unroll
        for (int i = 0; i < 8; i++) {
            const float2 v = *reinterpret_cast<const float2*>(
                tables + ((long)(gh + i) * M_TBL + ii[i]) * 2);
            buf0[(2 * (gh + i)    ) * STR + gp] = v.x;
            buf0[(2 * (gh + i) + 1) * STR + gp] = v.y;
        }
    }
    __syncthreads();

    for (long t = blockIdx.x; t < NTILES; t += GRID) {
        const long pbase = (long)t * TILE;
        const bool hasNext = (t + GRID) < NTILES;

        // idx LDG for NEXT tile (hidden under layer 1)
        int4 ni0 = make_int4(0,0,0,0), ni1 = make_int4(0,0,0,0);
        if (hasNext) {
            const int* ip = idx + ((t + GRID) * TILE + gp) * NHEADS + gh;
            ni0 = *reinterpret_cast<const int4*>(ip);
            ni1 = *reinterpret_cast<const int4*>(ip + 4);
        }

        // layer 1: buf0 -> buf1
        layer<1, D_IN>(buf0, buf1, jw, lane4);
        __syncthreads();                               // [1]

        // table LDGs for next tile (hidden under L2/L3)
        float2 nv[8];
        if (hasNext) {
            const int nii[8] = { ni0.x, ni0.y, ni0.z, ni0.w,
                                 ni1.x, ni1.y, ni1.z, ni1.w };
            #pragma unroll
            for (int i = 0; i < 8; i++)
                nv[i] = *reinterpret_cast<const float2*>(
                    tables + ((long)(gh + i) * M_TBL + nii[i]) * 2);
        }

        // layer 2: buf1 -> buf0
        layer<2, HID>(buf1, buf0, jw, lane4);
        __syncthreads();                               // [2]

        // layer 3: buf0 -> buf1
        layer<3, HID>(buf0, buf1, jw, lane4);
        __syncthreads();                               // [3]

        // buf0 is dead now: park NEXT tile's gather (concurrent with L4)
        if (hasNext) {
            #pragma unroll
            for (int i = 0; i < 8; i++) {
                buf0[(2 * (gh + i)    ) * STR + gp] = nv[i].x;
                buf0[(2 * (gh + i) + 1) * STR + gp] = nv[i].y;
            }
        }

        // layer 4: buf1 -> out, 2 threads/point (k halves) + shfl combine
        {
            const int p  = tid >> 1;
            const int kb = (tid & 1) * 32;
            float o0 = 0.f, o1 = 0.f, o2 = 0.f;
            #pragma unroll 8
            for (int k = kb; k < kb + 32; k++) {
                const float a = buf1[k * STR + p];
                o0 = fmaf(a, cW4[k * NOUT + 0], o0);
                o1 = fmaf(a, cW4[k * NOUT + 1], o1);
                o2 = fmaf(a, cW4[k * NOUT + 2], o2);
            }
            o0 += __shfl_down_sync(0xFFFFFFFFu, o0, 1);
            o1 += __shfl_down_sync(0xFFFFFFFFu, o1, 1);
            o2 += __shfl_down_sync(0xFFFFFFFFu, o2, 1);
            if ((tid & 1) == 0) {
                float* op = out + (pbase + p) * NOUT;
                op[0] = o0 + cb4[0];
                op[1] = o1 + cb4[1];
                op[2] = o2 + cb4[2];
            }
        }
        __syncthreads();                               // [4]
    }
}

extern "C" void kernel_launch(void* const* d_in, const int* in_sizes, int n_in,
                              void* d_out, int out_size)
{
    static int init = 0;
    if (!init) {
        cudaFuncSetAttribute(ngp_pp_kernel,
                             cudaFuncAttributeMaxDynamicSharedMemorySize,
                             SMEM_BYTES);
        init = 1;
    }

    cudaMemcpyToSymbolAsync(cW1, d_in[2], D_IN*HID*sizeof(float), 0,
                            cudaMemcpyDeviceToDevice, 0);
    cudaMemcpyToSymbolAsync(cb1, d_in[3], HID*sizeof(float), 0,
                            cudaMemcpyDeviceToDevice, 0);
    cudaMemcpyToSymbolAsync(cW2, d_in[4], HID*HID*sizeof(float), 0,
                            cudaMemcpyDeviceToDevice, 0);
    cudaMemcpyToSymbolAsync(cb2, d_in[5], HID*sizeof(float), 0,
                            cudaMemcpyDeviceToDevice, 0);
    cudaMemcpyToSymbolAsync(cW3, d_in[6], HID*HID*sizeof(float), 0,
                            cudaMemcpyDeviceToDevice, 0);
    cudaMemcpyToSymbolAsync(cb3, d_in[7], HID*sizeof(float), 0,
                            cudaMemcpyDeviceToDevice, 0);
    cudaMemcpyToSymbolAsync(cW4, d_in[8], HID*NOUT*sizeof(float), 0,
                            cudaMemcpyDeviceToDevice, 0);
    cudaMemcpyToSymbolAsync(cb4, d_in[9], NOUT*sizeof(float), 0,
                            cudaMemcpyDeviceToDevice, 0);

    ngp_pp_kernel<<<GRID, THREADS, SMEM_BYTES>>>(
        (const int*)d_in[0], (const float*)d_in[1], (float*)d_out);
}